// round 1
// baseline (speedup 1.0000x reference)
#include <cuda_runtime.h>
#include <math.h>

#define N_USERS   100000
#define N_RECIPES 50000
#define NE        600000
#define NL        200000
#define HDIM      128
#define OUTDIM    64

// ---------------- scratch (no allocation allowed) ----------------
__device__ __align__(128) float g_hu[(size_t)N_USERS * HDIM];
__device__ __align__(128) float g_hr[(size_t)N_RECIPES * HDIM];
__device__ __align__(128) float g_mean_r[(size_t)N_RECIPES * HDIM];
__device__ __align__(128) float g_mean_u[(size_t)N_USERS * HDIM];
__device__ __align__(128) float g_r1[(size_t)N_RECIPES * HDIM];
__device__ __align__(128) float g_u1[(size_t)N_USERS * HDIM];
__device__ __align__(128) float g_mr2[(size_t)N_RECIPES * HDIM];
__device__ __align__(128) float g_mu2[(size_t)N_USERS * HDIM];
__device__ __align__(128) float g_zr[(size_t)N_RECIPES * OUTDIM];
__device__ __align__(128) float g_zu[(size_t)N_USERS * OUTDIM];

__device__ __align__(128) int g_off_r[N_RECIPES + 1];
__device__ __align__(128) int g_off_u[N_USERS + 1];
__device__ __align__(128) int g_cur_r[N_RECIPES];
__device__ __align__(128) int g_cur_u[N_USERS];
__device__ __align__(128) int g_adj_r[NE];   // for each recipe: incident user ids
__device__ __align__(128) int g_adj_u[NE];   // for each user: incident recipe ids
__device__ __align__(128) int g_bsum_r[64];
__device__ __align__(128) int g_bsum_u[128];

// ---------------- small utility kernels ----------------
__global__ void zero_int(int* __restrict__ p, int n) {
    int i = blockIdx.x * blockDim.x + threadIdx.x;
    if (i < n) p[i] = 0;
}

__global__ void copy_int(int* __restrict__ dst, const int* __restrict__ src, int n) {
    int i = blockIdx.x * blockDim.x + threadIdx.x;
    if (i < n) dst[i] = src[i];
}

__global__ void count_deg(const int* __restrict__ es, const int* __restrict__ ed,
                          int* __restrict__ deg_u, int* __restrict__ deg_r, int E) {
    int e = blockIdx.x * blockDim.x + threadIdx.x;
    if (e < E) {
        atomicAdd(&deg_u[es[e]], 1);
        atomicAdd(&deg_r[ed[e]], 1);
    }
}

// block-level inclusive scan over 1024-element chunks; off[i+1] = inclusive
__global__ void scan_chunks(const int* __restrict__ deg, int* __restrict__ off,
                            int* __restrict__ bsum, int n) {
    __shared__ int sh[1024];
    int t = threadIdx.x;
    int gid = blockIdx.x * 1024 + t;
    int v = (gid < n) ? deg[gid] : 0;
    sh[t] = v;
    __syncthreads();
    #pragma unroll
    for (int d = 1; d < 1024; d <<= 1) {
        int add = (t >= d) ? sh[t - d] : 0;
        __syncthreads();
        sh[t] += add;
        __syncthreads();
    }
    if (gid < n) off[gid + 1] = sh[t];
    if (t == 1023) bsum[blockIdx.x] = sh[1023];
    if (gid == 0) off[0] = 0;
}

__global__ void scan_bsums(int* __restrict__ bsum, int nb) {
    if (threadIdx.x == 0 && blockIdx.x == 0) {
        int acc = 0;
        for (int i = 0; i < nb; i++) { int t = bsum[i]; bsum[i] = acc; acc += t; }
    }
}

__global__ void add_bsums(int* __restrict__ off, const int* __restrict__ bsum, int n) {
    int gid = blockIdx.x * 1024 + threadIdx.x;
    if (gid < n) off[gid + 1] += bsum[blockIdx.x];
}

__global__ void fill_adj(const int* __restrict__ es, const int* __restrict__ ed,
                         int* __restrict__ cur_u, int* __restrict__ cur_r,
                         int* __restrict__ adj_u, int* __restrict__ adj_r, int E) {
    int e = blockIdx.x * blockDim.x + threadIdx.x;
    if (e < E) {
        int s = es[e], d = ed[e];
        adj_r[atomicAdd(&cur_r[d], 1)] = s;
        adj_u[atomicAdd(&cur_u[s], 1)] = d;
    }
}

// ---------------- scatter-mean as gather (one warp per dst node, H=128) ----------------
__global__ void aggregate_mean(const float* __restrict__ feat,
                               const int* __restrict__ off, const int* __restrict__ adj,
                               float* __restrict__ out, int n) {
    int w = (blockIdx.x * blockDim.x + threadIdx.x) >> 5;
    if (w >= n) return;
    int lane = threadIdx.x & 31;
    int s = off[w], e = off[w + 1];
    float4 acc = make_float4(0.f, 0.f, 0.f, 0.f);
    for (int i = s; i < e; i++) {
        int nb = __ldg(&adj[i]);
        float4 v = *reinterpret_cast<const float4*>(&feat[(size_t)nb * HDIM + lane * 4]);
        acc.x += v.x; acc.y += v.y; acc.z += v.z; acc.w += v.w;
    }
    float inv = (e > s) ? 1.f / (float)(e - s) : 0.f;
    acc.x *= inv; acc.y *= inv; acc.z *= inv; acc.w *= inv;
    *reinterpret_cast<float4*>(&out[(size_t)w * HDIM + lane * 4]) = acc;
}

// ---------------- fused (A@WA.T [+ B@WB.T] + bias [+relu]) ----------------
// W layout: [J][K] row-major (as produced by numpy), out = [n][J]
template <int K, int ROWS, int J>
__device__ __forceinline__ void gemm_accum(
    const float* __restrict__ src, const float* __restrict__ w,
    int n, int row0, int tid, int ct, int rt,
    float (*As)[ROWS + 4], float (*Ws)[J + 4], float acc[4][8]) {
    for (int kb = 0; kb < K; kb += 32) {
        // A tile: ROWS x 32 (k fastest in global, stored k-major in smem)
        #pragma unroll
        for (int i = 0; i < (ROWS * 32) / 256; ++i) {
            int lin = tid + i * 256;
            int r = lin >> 5, kk = lin & 31;
            int gr = row0 + r;
            As[kk][r] = (gr < n) ? __ldg(&src[(size_t)gr * K + kb + kk]) : 0.f;
        }
        // W tile: J x 32 -> smem [kk][j]
        #pragma unroll
        for (int i = 0; i < (J * 32) / 256; ++i) {
            int lin = tid + i * 256;
            int j = lin >> 5, kk = lin & 31;
            Ws[kk][j] = __ldg(&w[(size_t)j * K + kb + kk]);
        }
        __syncthreads();
        #pragma unroll
        for (int k = 0; k < 32; ++k) {
            float4 a4 = *reinterpret_cast<const float4*>(&As[k][rt * 4]);
            float4 w0 = *reinterpret_cast<const float4*>(&Ws[k][ct * 8]);
            float4 w1 = *reinterpret_cast<const float4*>(&Ws[k][ct * 8 + 4]);
            float av[4] = {a4.x, a4.y, a4.z, a4.w};
            float wv[8] = {w0.x, w0.y, w0.z, w0.w, w1.x, w1.y, w1.z, w1.w};
            #pragma unroll
            for (int r = 0; r < 4; ++r)
                #pragma unroll
                for (int c = 0; c < 8; ++c)
                    acc[r][c] = fmaf(av[r], wv[c], acc[r][c]);
        }
        __syncthreads();
    }
}

template <int KA, int KB, int J, bool RELU>
__global__ __launch_bounds__(256)
void fused_linear(const float* __restrict__ A, const float* __restrict__ WA,
                  const float* __restrict__ B, const float* __restrict__ WB,
                  const float* __restrict__ bias, float* __restrict__ out, int n) {
    constexpr int CT = J / 8;        // threads along columns
    constexpr int RT = 256 / CT;     // threads along rows
    constexpr int ROWS = RT * 4;     // rows per block
    __shared__ float As[32][ROWS + 4];
    __shared__ float Ws[32][J + 4];

    int tid = threadIdx.x;
    int ct = tid % CT, rt = tid / CT;
    int row0 = blockIdx.x * ROWS;

    float acc[4][8];
    #pragma unroll
    for (int r = 0; r < 4; r++)
        #pragma unroll
        for (int c = 0; c < 8; c++) acc[r][c] = 0.f;

    gemm_accum<KA, ROWS, J>(A, WA, n, row0, tid, ct, rt, As, Ws, acc);
    if constexpr (KB > 0)
        gemm_accum<KB, ROWS, J>(B, WB, n, row0, tid, ct, rt, As, Ws, acc);

    #pragma unroll
    for (int r = 0; r < 4; r++) {
        int gr = row0 + rt * 4 + r;
        if (gr < n) {
            float v[8];
            #pragma unroll
            for (int c = 0; c < 8; c++) {
                float x = acc[r][c] + __ldg(&bias[ct * 8 + c]);
                if constexpr (RELU) x = fmaxf(x, 0.f);
                v[c] = x;
            }
            float* op = &out[(size_t)gr * J + ct * 8];
            *reinterpret_cast<float4*>(op)     = make_float4(v[0], v[1], v[2], v[3]);
            *reinterpret_cast<float4*>(op + 4) = make_float4(v[4], v[5], v[6], v[7]);
        }
    }
}

// ---------------- decoder: normalized dot on labeled pairs ----------------
__global__ void decoder_kernel(const float* __restrict__ zu, const float* __restrict__ zr,
                               const int* __restrict__ ls, const int* __restrict__ ld,
                               float* __restrict__ out, int L) {
    int w = (blockIdx.x * blockDim.x + threadIdx.x) >> 5;
    if (w >= L) return;
    int lane = threadIdx.x & 31;
    int s = __ldg(&ls[w]), d = __ldg(&ld[w]);
    float2 a = *reinterpret_cast<const float2*>(&zu[(size_t)s * OUTDIM + lane * 2]);
    float2 b = *reinterpret_cast<const float2*>(&zr[(size_t)d * OUTDIM + lane * 2]);
    float dot = a.x * b.x + a.y * b.y;
    float na = a.x * a.x + a.y * a.y;
    float nb = b.x * b.x + b.y * b.y;
    #pragma unroll
    for (int o = 16; o > 0; o >>= 1) {
        dot += __shfl_xor_sync(0xffffffffu, dot, o);
        na  += __shfl_xor_sync(0xffffffffu, na, o);
        nb  += __shfl_xor_sync(0xffffffffu, nb, o);
    }
    if (lane == 0)
        out[w] = dot / (fmaxf(sqrtf(na), 1e-12f) * fmaxf(sqrtf(nb), 1e-12f));
}

// ---------------- launch ----------------
extern "C" void kernel_launch(void* const* d_in, const int* in_sizes, int n_in,
                              void* d_out, int out_size) {
    const float* x_user   = (const float*)d_in[0];
    const float* x_recipe = (const float*)d_in[1];
    const int* edge_src = (const int*)d_in[2];
    const int* edge_dst = (const int*)d_in[3];
    const int* lbl_src  = (const int*)d_in[4];
    const int* lbl_dst  = (const int*)d_in[5];
    const float* Wu   = (const float*)d_in[6];
    const float* bu   = (const float*)d_in[7];
    const float* Wrec = (const float*)d_in[8];
    const float* brec = (const float*)d_in[9];
    const float* c1urWl = (const float*)d_in[10];
    const float* c1urbl = (const float*)d_in[11];
    const float* c1urWr = (const float*)d_in[12];
    const float* c1ruWl = (const float*)d_in[13];
    const float* c1rubl = (const float*)d_in[14];
    const float* c1ruWr = (const float*)d_in[15];
    const float* c2urWl = (const float*)d_in[16];
    const float* c2urbl = (const float*)d_in[17];
    const float* c2urWr = (const float*)d_in[18];
    const float* c2ruWl = (const float*)d_in[19];
    const float* c2rubl = (const float*)d_in[20];
    const float* c2ruWr = (const float*)d_in[21];
    float* out = (float*)d_out;

    float *hu, *hr, *mean_r, *mean_u, *r1, *u1, *mr2, *mu2, *zr, *zu;
    int *off_r, *off_u, *cur_r, *cur_u, *adj_r, *adj_u, *bs_r, *bs_u;
    cudaGetSymbolAddress((void**)&hu, g_hu);
    cudaGetSymbolAddress((void**)&hr, g_hr);
    cudaGetSymbolAddress((void**)&mean_r, g_mean_r);
    cudaGetSymbolAddress((void**)&mean_u, g_mean_u);
    cudaGetSymbolAddress((void**)&r1, g_r1);
    cudaGetSymbolAddress((void**)&u1, g_u1);
    cudaGetSymbolAddress((void**)&mr2, g_mr2);
    cudaGetSymbolAddress((void**)&mu2, g_mu2);
    cudaGetSymbolAddress((void**)&zr, g_zr);
    cudaGetSymbolAddress((void**)&zu, g_zu);
    cudaGetSymbolAddress((void**)&off_r, g_off_r);
    cudaGetSymbolAddress((void**)&off_u, g_off_u);
    cudaGetSymbolAddress((void**)&cur_r, g_cur_r);
    cudaGetSymbolAddress((void**)&cur_u, g_cur_u);
    cudaGetSymbolAddress((void**)&adj_r, g_adj_r);
    cudaGetSymbolAddress((void**)&adj_u, g_adj_u);
    cudaGetSymbolAddress((void**)&bs_r, g_bsum_r);
    cudaGetSymbolAddress((void**)&bs_u, g_bsum_u);

    const int CH_U = (N_USERS + 1023) / 1024;    // 98
    const int CH_R = (N_RECIPES + 1023) / 1024;  // 49

    // --- CSR build ---
    zero_int<<<(N_USERS + 255) / 256, 256>>>(cur_u, N_USERS);
    zero_int<<<(N_RECIPES + 255) / 256, 256>>>(cur_r, N_RECIPES);
    count_deg<<<(NE + 255) / 256, 256>>>(edge_src, edge_dst, cur_u, cur_r, NE);
    scan_chunks<<<CH_U, 1024>>>(cur_u, off_u, bs_u, N_USERS);
    scan_bsums<<<1, 1>>>(bs_u, CH_U);
    add_bsums<<<CH_U, 1024>>>(off_u, bs_u, N_USERS);
    scan_chunks<<<CH_R, 1024>>>(cur_r, off_r, bs_r, N_RECIPES);
    scan_bsums<<<1, 1>>>(bs_r, CH_R);
    add_bsums<<<CH_R, 1024>>>(off_r, bs_r, N_RECIPES);
    copy_int<<<(N_USERS + 255) / 256, 256>>>(cur_u, off_u, N_USERS);
    copy_int<<<(N_RECIPES + 255) / 256, 256>>>(cur_r, off_r, N_RECIPES);
    fill_adj<<<(NE + 255) / 256, 256>>>(edge_src, edge_dst, cur_u, cur_r, adj_u, adj_r, NE);

    // --- input projections ---
    fused_linear<128, 0, 128, false><<<(N_USERS + 63) / 64, 256>>>(
        x_user, Wu, nullptr, nullptr, bu, hu, N_USERS);
    fused_linear<256, 0, 128, false><<<(N_RECIPES + 63) / 64, 256>>>(
        x_recipe, Wrec, nullptr, nullptr, brec, hr, N_RECIPES);

    // --- conv1 ---
    aggregate_mean<<<(N_RECIPES * 32 + 255) / 256, 256>>>(hu, off_r, adj_r, mean_r, N_RECIPES);
    aggregate_mean<<<(N_USERS * 32 + 255) / 256, 256>>>(hr, off_u, adj_u, mean_u, N_USERS);
    fused_linear<128, 128, 128, true><<<(N_RECIPES + 63) / 64, 256>>>(
        mean_r, c1urWl, hr, c1urWr, c1urbl, r1, N_RECIPES);
    fused_linear<128, 128, 128, true><<<(N_USERS + 63) / 64, 256>>>(
        mean_u, c1ruWl, hu, c1ruWr, c1rubl, u1, N_USERS);

    // --- conv2 ---
    aggregate_mean<<<(N_RECIPES * 32 + 255) / 256, 256>>>(u1, off_r, adj_r, mr2, N_RECIPES);
    aggregate_mean<<<(N_USERS * 32 + 255) / 256, 256>>>(r1, off_u, adj_u, mu2, N_USERS);
    fused_linear<128, 128, 64, false><<<(N_RECIPES + 127) / 128, 256>>>(
        mr2, c2urWl, r1, c2urWr, c2urbl, zr, N_RECIPES);
    fused_linear<128, 128, 64, false><<<(N_USERS + 127) / 128, 256>>>(
        mu2, c2ruWl, u1, c2ruWr, c2rubl, zu, N_USERS);

    // --- decoder ---
    decoder_kernel<<<(NL + 7) / 8, 256>>>(zu, zr, lbl_src, lbl_dst, out, NL);
}

// round 3
// speedup vs baseline: 2.5548x; 2.5548x over previous
#include <cuda_runtime.h>
#include <math.h>
#include <stdint.h>

#define N_USERS   100000
#define N_RECIPES 50000
#define NE        600000
#define NL        200000
#define HDIM      128
#define OUTDIM    64

// ---------------- scratch (no allocation allowed) ----------------
__device__ __align__(128) float g_hu[(size_t)N_USERS * HDIM];
__device__ __align__(128) float g_hr[(size_t)N_RECIPES * HDIM];
__device__ __align__(128) float g_mean_r[(size_t)N_RECIPES * HDIM];
__device__ __align__(128) float g_mean_u[(size_t)N_USERS * HDIM];
__device__ __align__(128) float g_r1[(size_t)N_RECIPES * HDIM];
__device__ __align__(128) float g_u1[(size_t)N_USERS * HDIM];
__device__ __align__(128) float g_mr2[(size_t)N_RECIPES * HDIM];
__device__ __align__(128) float g_mu2[(size_t)N_USERS * HDIM];
__device__ __align__(128) float g_zr[(size_t)N_RECIPES * OUTDIM];
__device__ __align__(128) float g_zu[(size_t)N_USERS * OUTDIM];

__device__ __align__(128) int g_off_r[N_RECIPES + 1];
__device__ __align__(128) int g_off_u[N_USERS + 1];
__device__ __align__(128) int g_cur_r[N_RECIPES];
__device__ __align__(128) int g_cur_u[N_USERS];
__device__ __align__(128) int g_adj_r[NE];
__device__ __align__(128) int g_adj_u[NE];
__device__ __align__(128) int g_bsum_r[64];
__device__ __align__(128) int g_bsum_u[128];

// ---------------- tf32 mma helpers (sm_80+ legacy path, no 'a' features) ----------------
__device__ __forceinline__ float f2tf32(float f) {
    uint32_t r;
    asm("cvt.rna.tf32.f32 %0, %1;" : "=r"(r) : "f"(f));
    return __uint_as_float(r);
}

__device__ __forceinline__ float4 cvt4(float4 v) {
    return make_float4(f2tf32(v.x), f2tf32(v.y), f2tf32(v.z), f2tf32(v.w));
}

__device__ __forceinline__ void mma_tf32(float* d,
                                         uint32_t a0, uint32_t a1, uint32_t a2, uint32_t a3,
                                         uint32_t b0, uint32_t b1) {
    asm volatile(
        "mma.sync.aligned.m16n8k8.row.col.f32.tf32.tf32.f32 "
        "{%0,%1,%2,%3}, {%4,%5,%6,%7}, {%8,%9}, {%0,%1,%2,%3};"
        : "+f"(d[0]), "+f"(d[1]), "+f"(d[2]), "+f"(d[3])
        : "r"(a0), "r"(a1), "r"(a2), "r"(a3), "r"(b0), "r"(b1));
}

// ---------------- fused tf32 tensor-core GEMM ----------------
// out[n, J] = A[n, KA] @ WA[J, KA]^T (+ B[n, KB] @ WB[J, KB]^T) + bias (+relu)
// Block: 256 thr, tile 128 x J.  Warp grid 4(m) x 2(n); warp tile 32 x J/2.
// K chunked by 32, double-buffered smem, register prefetch.
template <int KA, int KB, int J, bool RELU>
__global__ __launch_bounds__(256, 1)
void gemm_mma(const float* __restrict__ A, const float* __restrict__ WA,
              const float* __restrict__ B, const float* __restrict__ WB,
              const float* __restrict__ bias, float* __restrict__ out, int n) {
    constexpr int NCH = (KA + KB) / 32;
    constexpr int CHA = KA / 32;
    constexpr int LDS = 36;                 // padded row (floats): conflict-free frags
    constexpr int NT  = J / 16;             // n-tiles (8 cols) per warp (8 for J=128)
    constexpr int WI  = (J * 8) / 256;      // W float4s per thread per chunk

    extern __shared__ float sm[];
    float* AsB = sm;                        // [2][128][LDS]
    float* WsB = sm + 2 * 128 * LDS;        // [2][J][LDS]

    const int tid  = threadIdx.x;
    const int lane = tid & 31;
    const int wid  = tid >> 5;
    const int wm   = wid & 3;               // 4 warps along m
    const int wn   = wid >> 2;              // 2 warps along n
    const int qr   = lane >> 2;             // 0..7
    const int qc   = lane & 3;              // 0..3
    const int row0 = blockIdx.x * 128;

    float acc[2][NT][4];
    #pragma unroll
    for (int mt = 0; mt < 2; mt++)
        #pragma unroll
        for (int nt = 0; nt < NT; nt++)
            #pragma unroll
            for (int q = 0; q < 4; q++) acc[mt][nt][q] = 0.f;

    float4 pa[4], pw[WI];

    auto fetch = [&](int c) {
        const float* src; const float* w; int ld, k0;
        if (c < CHA) { src = A; w = WA; ld = KA; k0 = c * 32; }
        else         { src = B; w = WB; ld = KB; k0 = (c - CHA) * 32; }
        #pragma unroll
        for (int i = 0; i < 4; i++) {
            int lin = tid + i * 256;
            int r = lin >> 3, q = lin & 7;
            int gr = row0 + r;
            pa[i] = (gr < n)
                ? *reinterpret_cast<const float4*>(&src[(size_t)gr * ld + k0 + q * 4])
                : make_float4(0.f, 0.f, 0.f, 0.f);
        }
        #pragma unroll
        for (int i = 0; i < WI; i++) {
            int lin = tid + i * 256;
            int j = lin >> 3, q = lin & 7;
            pw[i] = *reinterpret_cast<const float4*>(&w[(size_t)j * ld + k0 + q * 4]);
        }
    };

    auto store = [&](int b) {
        float* as = AsB + b * 128 * LDS;
        float* ws = WsB + b * J * LDS;
        #pragma unroll
        for (int i = 0; i < 4; i++) {
            int lin = tid + i * 256;
            int r = lin >> 3, q = lin & 7;
            *reinterpret_cast<float4*>(&as[r * LDS + q * 4]) = cvt4(pa[i]);
        }
        #pragma unroll
        for (int i = 0; i < WI; i++) {
            int lin = tid + i * 256;
            int j = lin >> 3, q = lin & 7;
            *reinterpret_cast<float4*>(&ws[j * LDS + q * 4]) = cvt4(pw[i]);
        }
    };

    fetch(0);
    store(0);
    __syncthreads();

    for (int c = 0; c < NCH; ++c) {
        const int b = c & 1;
        if (c + 1 < NCH) fetch(c + 1);

        const float* as = AsB + b * 128 * LDS + (wm * 32) * LDS;
        const float* ws = WsB + b * J * LDS + (wn * NT * 8) * LDS;

        #pragma unroll
        for (int ks = 0; ks < 4; ++ks) {
            const int k0 = ks * 8 + qc;
            uint32_t af[2][4];
            #pragma unroll
            for (int mt = 0; mt < 2; mt++) {
                const float* ap = as + (mt * 16 + qr) * LDS;
                af[mt][0] = __float_as_uint(ap[k0]);
                af[mt][1] = __float_as_uint(ap[8 * LDS + k0]);
                af[mt][2] = __float_as_uint(ap[k0 + 4]);
                af[mt][3] = __float_as_uint(ap[8 * LDS + k0 + 4]);
            }
            uint32_t bf[NT][2];
            #pragma unroll
            for (int nt = 0; nt < NT; nt++) {
                const float* bp = ws + (nt * 8 + qr) * LDS;
                bf[nt][0] = __float_as_uint(bp[k0]);
                bf[nt][1] = __float_as_uint(bp[k0 + 4]);
            }
            #pragma unroll
            for (int mt = 0; mt < 2; mt++)
                #pragma unroll
                for (int nt = 0; nt < NT; nt++)
                    mma_tf32(acc[mt][nt],
                             af[mt][0], af[mt][1], af[mt][2], af[mt][3],
                             bf[nt][0], bf[nt][1]);
        }

        if (c + 1 < NCH) {
            store(b ^ 1);
            __syncthreads();
        }
    }

    // epilogue: C frag (m16n8): {c0,c1} row=qr col=2qc; {c2,c3} row=qr+8
    #pragma unroll
    for (int mt = 0; mt < 2; mt++) {
        #pragma unroll
        for (int nt = 0; nt < NT; nt++) {
            int gcol = wn * NT * 8 + nt * 8 + 2 * qc;
            float bx = __ldg(&bias[gcol]), by = __ldg(&bias[gcol + 1]);
            int r0 = row0 + wm * 32 + mt * 16 + qr;
            float v0 = acc[mt][nt][0] + bx, v1 = acc[mt][nt][1] + by;
            float v2 = acc[mt][nt][2] + bx, v3 = acc[mt][nt][3] + by;
            if (RELU) {
                v0 = fmaxf(v0, 0.f); v1 = fmaxf(v1, 0.f);
                v2 = fmaxf(v2, 0.f); v3 = fmaxf(v3, 0.f);
            }
            if (r0 < n)
                *reinterpret_cast<float2*>(&out[(size_t)r0 * J + gcol]) = make_float2(v0, v1);
            if (r0 + 8 < n)
                *reinterpret_cast<float2*>(&out[(size_t)(r0 + 8) * J + gcol]) = make_float2(v2, v3);
        }
    }
}

// ---------------- small utility kernels ----------------
__global__ void zero_int(int* __restrict__ p, int n) {
    int i = blockIdx.x * blockDim.x + threadIdx.x;
    if (i < n) p[i] = 0;
}

__global__ void copy_int(int* __restrict__ dst, const int* __restrict__ src, int n) {
    int i = blockIdx.x * blockDim.x + threadIdx.x;
    if (i < n) dst[i] = src[i];
}

__global__ void count_deg(const int* __restrict__ es, const int* __restrict__ ed,
                          int* __restrict__ deg_u, int* __restrict__ deg_r, int E) {
    int e = blockIdx.x * blockDim.x + threadIdx.x;
    if (e < E) {
        atomicAdd(&deg_u[es[e]], 1);
        atomicAdd(&deg_r[ed[e]], 1);
    }
}

__global__ void scan_chunks(const int* __restrict__ deg, int* __restrict__ off,
                            int* __restrict__ bsum, int n) {
    __shared__ int sh[1024];
    int t = threadIdx.x;
    int gid = blockIdx.x * 1024 + t;
    int v = (gid < n) ? deg[gid] : 0;
    sh[t] = v;
    __syncthreads();
    #pragma unroll
    for (int d = 1; d < 1024; d <<= 1) {
        int add = (t >= d) ? sh[t - d] : 0;
        __syncthreads();
        sh[t] += add;
        __syncthreads();
    }
    if (gid < n) off[gid + 1] = sh[t];
    if (t == 1023) bsum[blockIdx.x] = sh[1023];
    if (gid == 0) off[0] = 0;
}

__global__ void scan_bsums(int* __restrict__ bsum, int nb) {
    if (threadIdx.x == 0 && blockIdx.x == 0) {
        int acc = 0;
        for (int i = 0; i < nb; i++) { int t = bsum[i]; bsum[i] = acc; acc += t; }
    }
}

__global__ void add_bsums(int* __restrict__ off, const int* __restrict__ bsum, int n) {
    int gid = blockIdx.x * 1024 + threadIdx.x;
    if (gid < n) off[gid + 1] += bsum[blockIdx.x];
}

__global__ void fill_adj(const int* __restrict__ es, const int* __restrict__ ed,
                         int* __restrict__ cur_u, int* __restrict__ cur_r,
                         int* __restrict__ adj_u, int* __restrict__ adj_r, int E) {
    int e = blockIdx.x * blockDim.x + threadIdx.x;
    if (e < E) {
        int s = es[e], d = ed[e];
        adj_r[atomicAdd(&cur_r[d], 1)] = s;
        adj_u[atomicAdd(&cur_u[s], 1)] = d;
    }
}

// ---------------- scatter-mean as gather (one warp per dst node, H=128) ----------------
__global__ void aggregate_mean(const float* __restrict__ feat,
                               const int* __restrict__ off, const int* __restrict__ adj,
                               float* __restrict__ out, int n) {
    int w = (blockIdx.x * blockDim.x + threadIdx.x) >> 5;
    if (w >= n) return;
    int lane = threadIdx.x & 31;
    int s = off[w], e = off[w + 1];
    float4 acc = make_float4(0.f, 0.f, 0.f, 0.f);
    for (int i = s; i < e; i++) {
        int nb = __ldg(&adj[i]);
        float4 v = *reinterpret_cast<const float4*>(&feat[(size_t)nb * HDIM + lane * 4]);
        acc.x += v.x; acc.y += v.y; acc.z += v.z; acc.w += v.w;
    }
    float inv = (e > s) ? 1.f / (float)(e - s) : 0.f;
    acc.x *= inv; acc.y *= inv; acc.z *= inv; acc.w *= inv;
    *reinterpret_cast<float4*>(&out[(size_t)w * HDIM + lane * 4]) = acc;
}

// ---------------- decoder ----------------
__global__ void decoder_kernel(const float* __restrict__ zu, const float* __restrict__ zr,
                               const int* __restrict__ ls, const int* __restrict__ ld,
                               float* __restrict__ out, int L) {
    int w = (blockIdx.x * blockDim.x + threadIdx.x) >> 5;
    if (w >= L) return;
    int lane = threadIdx.x & 31;
    int s = __ldg(&ls[w]), d = __ldg(&ld[w]);
    float2 a = *reinterpret_cast<const float2*>(&zu[(size_t)s * OUTDIM + lane * 2]);
    float2 b = *reinterpret_cast<const float2*>(&zr[(size_t)d * OUTDIM + lane * 2]);
    float dot = a.x * b.x + a.y * b.y;
    float na = a.x * a.x + a.y * a.y;
    float nb = b.x * b.x + b.y * b.y;
    #pragma unroll
    for (int o = 16; o > 0; o >>= 1) {
        dot += __shfl_xor_sync(0xffffffffu, dot, o);
        na  += __shfl_xor_sync(0xffffffffu, na, o);
        nb  += __shfl_xor_sync(0xffffffffu, nb, o);
    }
    if (lane == 0)
        out[w] = dot / (fmaxf(sqrtf(na), 1e-12f) * fmaxf(sqrtf(nb), 1e-12f));
}

// ---------------- launch ----------------
extern "C" void kernel_launch(void* const* d_in, const int* in_sizes, int n_in,
                              void* d_out, int out_size) {
    const float* x_user   = (const float*)d_in[0];
    const float* x_recipe = (const float*)d_in[1];
    const int* edge_src = (const int*)d_in[2];
    const int* edge_dst = (const int*)d_in[3];
    const int* lbl_src  = (const int*)d_in[4];
    const int* lbl_dst  = (const int*)d_in[5];
    const float* Wu   = (const float*)d_in[6];
    const float* bu   = (const float*)d_in[7];
    const float* Wrec = (const float*)d_in[8];
    const float* brec = (const float*)d_in[9];
    const float* c1urWl = (const float*)d_in[10];
    const float* c1urbl = (const float*)d_in[11];
    const float* c1urWr = (const float*)d_in[12];
    const float* c1ruWl = (const float*)d_in[13];
    const float* c1rubl = (const float*)d_in[14];
    const float* c1ruWr = (const float*)d_in[15];
    const float* c2urWl = (const float*)d_in[16];
    const float* c2urbl = (const float*)d_in[17];
    const float* c2urWr = (const float*)d_in[18];
    const float* c2ruWl = (const float*)d_in[19];
    const float* c2rubl = (const float*)d_in[20];
    const float* c2ruWr = (const float*)d_in[21];
    float* out = (float*)d_out;

    float *hu, *hr, *mean_r, *mean_u, *r1, *u1, *mr2, *mu2, *zr, *zu;
    int *off_r, *off_u, *cur_r, *cur_u, *adj_r, *adj_u, *bs_r, *bs_u;
    cudaGetSymbolAddress((void**)&hu, g_hu);
    cudaGetSymbolAddress((void**)&hr, g_hr);
    cudaGetSymbolAddress((void**)&mean_r, g_mean_r);
    cudaGetSymbolAddress((void**)&mean_u, g_mean_u);
    cudaGetSymbolAddress((void**)&r1, g_r1);
    cudaGetSymbolAddress((void**)&u1, g_u1);
    cudaGetSymbolAddress((void**)&mr2, g_mr2);
    cudaGetSymbolAddress((void**)&mu2, g_mu2);
    cudaGetSymbolAddress((void**)&zr, g_zr);
    cudaGetSymbolAddress((void**)&zu, g_zu);
    cudaGetSymbolAddress((void**)&off_r, g_off_r);
    cudaGetSymbolAddress((void**)&off_u, g_off_u);
    cudaGetSymbolAddress((void**)&cur_r, g_cur_r);
    cudaGetSymbolAddress((void**)&cur_u, g_cur_u);
    cudaGetSymbolAddress((void**)&adj_r, g_adj_r);
    cudaGetSymbolAddress((void**)&adj_u, g_adj_u);
    cudaGetSymbolAddress((void**)&bs_r, g_bsum_r);
    cudaGetSymbolAddress((void**)&bs_u, g_bsum_u);

    // dynamic smem: 2 stages * (A 128x36 + W Jx36) floats
    const int SM_H = 2 * (128 * 36 + 128 * 36) * 4;  // 73728 B (J=128)
    const int SM_O = 2 * (128 * 36 + 64 * 36) * 4;   // 55296 B (J=64)
    cudaFuncSetAttribute(gemm_mma<128, 0, 128, false>,
                         cudaFuncAttributeMaxDynamicSharedMemorySize, SM_H);
    cudaFuncSetAttribute(gemm_mma<256, 0, 128, false>,
                         cudaFuncAttributeMaxDynamicSharedMemorySize, SM_H);
    cudaFuncSetAttribute(gemm_mma<128, 128, 128, true>,
                         cudaFuncAttributeMaxDynamicSharedMemorySize, SM_H);
    cudaFuncSetAttribute(gemm_mma<128, 128, 64, false>,
                         cudaFuncAttributeMaxDynamicSharedMemorySize, SM_O);

    const int CH_U = (N_USERS + 1023) / 1024;
    const int CH_R = (N_RECIPES + 1023) / 1024;
    const int GB_U = (N_USERS + 127) / 128;
    const int GB_R = (N_RECIPES + 127) / 128;

    // --- CSR build ---
    zero_int<<<(N_USERS + 255) / 256, 256>>>(cur_u, N_USERS);
    zero_int<<<(N_RECIPES + 255) / 256, 256>>>(cur_r, N_RECIPES);
    count_deg<<<(NE + 255) / 256, 256>>>(edge_src, edge_dst, cur_u, cur_r, NE);
    scan_chunks<<<CH_U, 1024>>>(cur_u, off_u, bs_u, N_USERS);
    scan_bsums<<<1, 1>>>(bs_u, CH_U);
    add_bsums<<<CH_U, 1024>>>(off_u, bs_u, N_USERS);
    scan_chunks<<<CH_R, 1024>>>(cur_r, off_r, bs_r, N_RECIPES);
    scan_bsums<<<1, 1>>>(bs_r, CH_R);
    add_bsums<<<CH_R, 1024>>>(off_r, bs_r, N_RECIPES);
    copy_int<<<(N_USERS + 255) / 256, 256>>>(cur_u, off_u, N_USERS);
    copy_int<<<(N_RECIPES + 255) / 256, 256>>>(cur_r, off_r, N_RECIPES);
    fill_adj<<<(NE + 255) / 256, 256>>>(edge_src, edge_dst, cur_u, cur_r, adj_u, adj_r, NE);

    // --- input projections (tf32 mma) ---
    gemm_mma<128, 0, 128, false><<<GB_U, 256, SM_H>>>(
        x_user, Wu, nullptr, nullptr, bu, hu, N_USERS);
    gemm_mma<256, 0, 128, false><<<GB_R, 256, SM_H>>>(
        x_recipe, Wrec, nullptr, nullptr, brec, hr, N_RECIPES);

    // --- conv1 ---
    aggregate_mean<<<(N_RECIPES * 32 + 255) / 256, 256>>>(hu, off_r, adj_r, mean_r, N_RECIPES);
    aggregate_mean<<<(N_USERS * 32 + 255) / 256, 256>>>(hr, off_u, adj_u, mean_u, N_USERS);
    gemm_mma<128, 128, 128, true><<<GB_R, 256, SM_H>>>(
        mean_r, c1urWl, hr, c1urWr, c1urbl, r1, N_RECIPES);
    gemm_mma<128, 128, 128, true><<<GB_U, 256, SM_H>>>(
        mean_u, c1ruWl, hu, c1ruWr, c1rubl, u1, N_USERS);

    // --- conv2 ---
    aggregate_mean<<<(N_RECIPES * 32 + 255) / 256, 256>>>(u1, off_r, adj_r, mr2, N_RECIPES);
    aggregate_mean<<<(N_USERS * 32 + 255) / 256, 256>>>(r1, off_u, adj_u, mu2, N_USERS);
    gemm_mma<128, 128, 64, false><<<GB_R, 256, SM_O>>>(
        mr2, c2urWl, r1, c2urWr, c2urbl, zr, N_RECIPES);
    gemm_mma<128, 128, 64, false><<<GB_U, 256, SM_O>>>(
        mu2, c2ruWl, u1, c2ruWr, c2rubl, zu, N_USERS);

    // --- decoder ---
    decoder_kernel<<<(NL + 7) / 8, 256>>>(zu, zr, lbl_src, lbl_dst, out, NL);
}

// round 4
// speedup vs baseline: 2.7757x; 1.0865x over previous
#include <cuda_runtime.h>
#include <math.h>
#include <stdint.h>

#define N_USERS   100000
#define N_RECIPES 50000
#define NE        600000
#define NL        200000
#define HDIM      128
#define OUTDIM    64

// ---------------- scratch (no allocation allowed) ----------------
__device__ __align__(128) float g_hu[(size_t)N_USERS * HDIM];
__device__ __align__(128) float g_hr[(size_t)N_RECIPES * HDIM];
__device__ __align__(128) float g_mean_r[(size_t)N_RECIPES * HDIM];
__device__ __align__(128) float g_mean_u[(size_t)N_USERS * HDIM];
__device__ __align__(128) float g_r1[(size_t)N_RECIPES * HDIM];
__device__ __align__(128) float g_u1[(size_t)N_USERS * HDIM];
__device__ __align__(128) float g_mr2[(size_t)N_RECIPES * HDIM];
__device__ __align__(128) float g_mu2[(size_t)N_USERS * HDIM];
__device__ __align__(128) float g_zr[(size_t)N_RECIPES * OUTDIM];
__device__ __align__(128) float g_zu[(size_t)N_USERS * OUTDIM];

__device__ __align__(128) int g_off_r[N_RECIPES + 1];
__device__ __align__(128) int g_off_u[N_USERS + 1];
__device__ __align__(128) int g_cur_r[N_RECIPES];
__device__ __align__(128) int g_cur_u[N_USERS];
__device__ __align__(128) int g_adj_r[NE];
__device__ __align__(128) int g_adj_u[NE];
__device__ __align__(128) int g_bsum_r[64];
__device__ __align__(128) int g_bsum_u[128];

// pre-rounded tf32 weights (Wu, Wrec, c1urWl, c1urWr, c1ruWl, c1ruWr,
//                           c2urWl, c2urWr, c2ruWl, c2ruWr)
#define W_TOTAL 147456
__device__ __align__(128) float g_wts[W_TOTAL];

// ---------------- tf32 mma helpers (sm_80+ legacy path, no 'a' features) ----------------
__device__ __forceinline__ float f2tf32(float f) {
    uint32_t r;
    asm("cvt.rna.tf32.f32 %0, %1;" : "=r"(r) : "f"(f));
    return __uint_as_float(r);
}

__device__ __forceinline__ float4 cvt4(float4 v) {
    return make_float4(f2tf32(v.x), f2tf32(v.y), f2tf32(v.z), f2tf32(v.w));
}

__device__ __forceinline__ void mma_tf32(float* d,
                                         uint32_t a0, uint32_t a1, uint32_t a2, uint32_t a3,
                                         uint32_t b0, uint32_t b1) {
    asm volatile(
        "mma.sync.aligned.m16n8k8.row.col.f32.tf32.tf32.f32 "
        "{%0,%1,%2,%3}, {%4,%5,%6,%7}, {%8,%9}, {%0,%1,%2,%3};"
        : "+f"(d[0]), "+f"(d[1]), "+f"(d[2]), "+f"(d[3])
        : "r"(a0), "r"(a1), "r"(a2), "r"(a3), "r"(b0), "r"(b1));
}

__device__ __forceinline__ void cp_async16(uint32_t smem_dst, const void* gsrc) {
    asm volatile("cp.async.ca.shared.global [%0], [%1], 16;"
                 :: "r"(smem_dst), "l"(gsrc) : "memory");
}

// ---------------- weight prep: round all weights to tf32 once ----------------
__global__ void prep_weights(const float* __restrict__ w0, const float* __restrict__ w1,
                             const float* __restrict__ w2, const float* __restrict__ w3,
                             const float* __restrict__ w4, const float* __restrict__ w5,
                             const float* __restrict__ w6, const float* __restrict__ w7,
                             const float* __restrict__ w8, const float* __restrict__ w9,
                             float* __restrict__ wts) {
    int i = blockIdx.x * blockDim.x + threadIdx.x;
    const float* src; int off;
    if      (i <  16384) { src = w0; off = 0;      }
    else if (i <  49152) { src = w1; off = 16384;  }
    else if (i <  65536) { src = w2; off = 49152;  }
    else if (i <  81920) { src = w3; off = 65536;  }
    else if (i <  98304) { src = w4; off = 81920;  }
    else if (i < 114688) { src = w5; off = 98304;  }
    else if (i < 122880) { src = w6; off = 114688; }
    else if (i < 131072) { src = w7; off = 122880; }
    else if (i < 139264) { src = w8; off = 131072; }
    else if (i < W_TOTAL){ src = w9; off = 139264; }
    else return;
    wts[i] = f2tf32(src[i - off]);
}

// ---------------- fused tf32 tensor-core GEMM ----------------
// out[n, J] = A[n, KA] @ WA[J, KA]^T (+ B[n, KB] @ WB[J, KB]^T) + bias (+relu)
// Block: 256 thr, tile 128 x J. Warp grid 4(m) x 2(n); warp tile 32 x J/2.
// K chunked by 32, double-buffered smem. A: LDG->cvt->STS; W: cp.async (pre-rounded).
template <int KA, int KB, int J, bool RELU>
__global__ __launch_bounds__(256, 2)
void gemm_mma(const float* __restrict__ A, const float* __restrict__ WA,
              const float* __restrict__ B, const float* __restrict__ WB,
              const float* __restrict__ bias, float* __restrict__ out, int n) {
    constexpr int NCH = (KA + KB) / 32;
    constexpr int CHA = KA / 32;
    constexpr int LDS = 36;                 // padded row (floats): conflict-free frags
    constexpr int NT  = J / 16;             // n-tiles (8 cols) per warp
    constexpr int WI  = (J * 8) / 256;      // W 16B chunks per thread per K-chunk

    extern __shared__ float sm[];
    float* AsB = sm;                        // [2][128][LDS]
    float* WsB = sm + 2 * 128 * LDS;        // [2][J][LDS]

    const int tid  = threadIdx.x;
    const int lane = tid & 31;
    const int wid  = tid >> 5;
    const int wm   = wid & 3;
    const int wn   = wid >> 2;
    const int qr   = lane >> 2;
    const int qc   = lane & 3;
    const int row0 = blockIdx.x * 128;

    float acc[2][NT][4];
    #pragma unroll
    for (int mt = 0; mt < 2; mt++)
        #pragma unroll
        for (int nt = 0; nt < NT; nt++)
            #pragma unroll
            for (int q = 0; q < 4; q++) acc[mt][nt][q] = 0.f;

    float4 pa[4];

    auto fetchA = [&](int c) {
        const float* src = (c < CHA) ? A : B;
        const int ld = (c < CHA) ? KA : KB;
        const int k0 = (c < CHA) ? c * 32 : (c - CHA) * 32;
        #pragma unroll
        for (int i = 0; i < 4; i++) {
            int lin = tid + i * 256;
            int r = lin >> 3, q = lin & 7;
            int gr = row0 + r;
            pa[i] = (gr < n)
                ? *reinterpret_cast<const float4*>(&src[(size_t)gr * ld + k0 + q * 4])
                : make_float4(0.f, 0.f, 0.f, 0.f);
        }
    };

    auto issueW = [&](int c, int b) {
        const float* w = (c < CHA) ? WA : WB;
        const int ld = (c < CHA) ? KA : KB;
        const int k0 = (c < CHA) ? c * 32 : (c - CHA) * 32;
        uint32_t wbase = (uint32_t)__cvta_generic_to_shared(WsB + b * J * LDS);
        #pragma unroll
        for (int i = 0; i < WI; i++) {
            int lin = tid + i * 256;
            int j = lin >> 3, q = lin & 7;
            cp_async16(wbase + (uint32_t)(j * LDS + q * 4) * 4,
                       &w[(size_t)j * ld + k0 + q * 4]);
        }
        asm volatile("cp.async.commit_group;" ::: "memory");
    };

    auto storeA = [&](int b) {
        float* as = AsB + b * 128 * LDS;
        #pragma unroll
        for (int i = 0; i < 4; i++) {
            int lin = tid + i * 256;
            int r = lin >> 3, q = lin & 7;
            *reinterpret_cast<float4*>(&as[r * LDS + q * 4]) = cvt4(pa[i]);
        }
    };

    fetchA(0);
    issueW(0, 0);
    storeA(0);
    asm volatile("cp.async.wait_group 0;" ::: "memory");
    __syncthreads();

    for (int c = 0; c < NCH; ++c) {
        const int b = c & 1;
        if (c + 1 < NCH) {
            fetchA(c + 1);
            issueW(c + 1, b ^ 1);
        }

        const float* as = AsB + b * 128 * LDS + (wm * 32) * LDS;
        const float* ws = WsB + b * J * LDS + (wn * NT * 8) * LDS;

        #pragma unroll
        for (int ks = 0; ks < 4; ++ks) {
            const int k0 = ks * 8 + qc;
            uint32_t af[2][4];
            #pragma unroll
            for (int mt = 0; mt < 2; mt++) {
                const float* ap = as + (mt * 16 + qr) * LDS;
                af[mt][0] = __float_as_uint(ap[k0]);
                af[mt][1] = __float_as_uint(ap[8 * LDS + k0]);
                af[mt][2] = __float_as_uint(ap[k0 + 4]);
                af[mt][3] = __float_as_uint(ap[8 * LDS + k0 + 4]);
            }
            uint32_t bf[NT][2];
            #pragma unroll
            for (int nt = 0; nt < NT; nt++) {
                const float* bp = ws + (nt * 8 + qr) * LDS;
                bf[nt][0] = __float_as_uint(bp[k0]);
                bf[nt][1] = __float_as_uint(bp[k0 + 4]);
            }
            #pragma unroll
            for (int mt = 0; mt < 2; mt++)
                #pragma unroll
                for (int nt = 0; nt < NT; nt++)
                    mma_tf32(acc[mt][nt],
                             af[mt][0], af[mt][1], af[mt][2], af[mt][3],
                             bf[nt][0], bf[nt][1]);
        }

        if (c + 1 < NCH) {
            storeA(b ^ 1);
            asm volatile("cp.async.wait_group 0;" ::: "memory");
            __syncthreads();
        }
    }

    // epilogue: C frag (m16n8): {c0,c1} row=qr col=2qc; {c2,c3} row=qr+8
    #pragma unroll
    for (int mt = 0; mt < 2; mt++) {
        #pragma unroll
        for (int nt = 0; nt < NT; nt++) {
            int gcol = wn * NT * 8 + nt * 8 + 2 * qc;
            float bx = __ldg(&bias[gcol]), by = __ldg(&bias[gcol + 1]);
            int r0 = row0 + wm * 32 + mt * 16 + qr;
            float v0 = acc[mt][nt][0] + bx, v1 = acc[mt][nt][1] + by;
            float v2 = acc[mt][nt][2] + bx, v3 = acc[mt][nt][3] + by;
            if (RELU) {
                v0 = fmaxf(v0, 0.f); v1 = fmaxf(v1, 0.f);
                v2 = fmaxf(v2, 0.f); v3 = fmaxf(v3, 0.f);
            }
            if (r0 < n)
                *reinterpret_cast<float2*>(&out[(size_t)r0 * J + gcol]) = make_float2(v0, v1);
            if (r0 + 8 < n)
                *reinterpret_cast<float2*>(&out[(size_t)(r0 + 8) * J + gcol]) = make_float2(v2, v3);
        }
    }
}

// ---------------- small utility kernels ----------------
__global__ void zero_int(int* __restrict__ p, int n) {
    int i = blockIdx.x * blockDim.x + threadIdx.x;
    if (i < n) p[i] = 0;
}

__global__ void copy_int(int* __restrict__ dst, const int* __restrict__ src, int n) {
    int i = blockIdx.x * blockDim.x + threadIdx.x;
    if (i < n) dst[i] = src[i];
}

__global__ void count_deg(const int* __restrict__ es, const int* __restrict__ ed,
                          int* __restrict__ deg_u, int* __restrict__ deg_r, int E) {
    int e = blockIdx.x * blockDim.x + threadIdx.x;
    if (e < E) {
        atomicAdd(&deg_u[es[e]], 1);
        atomicAdd(&deg_r[ed[e]], 1);
    }
}

__global__ void scan_chunks(const int* __restrict__ deg, int* __restrict__ off,
                            int* __restrict__ bsum, int n) {
    __shared__ int sh[1024];
    int t = threadIdx.x;
    int gid = blockIdx.x * 1024 + t;
    int v = (gid < n) ? deg[gid] : 0;
    sh[t] = v;
    __syncthreads();
    #pragma unroll
    for (int d = 1; d < 1024; d <<= 1) {
        int add = (t >= d) ? sh[t - d] : 0;
        __syncthreads();
        sh[t] += add;
        __syncthreads();
    }
    if (gid < n) off[gid + 1] = sh[t];
    if (t == 1023) bsum[blockIdx.x] = sh[1023];
    if (gid == 0) off[0] = 0;
}

__global__ void scan_bsums(int* __restrict__ bsum, int nb) {
    if (threadIdx.x == 0 && blockIdx.x == 0) {
        int acc = 0;
        for (int i = 0; i < nb; i++) { int t = bsum[i]; bsum[i] = acc; acc += t; }
    }
}

__global__ void add_bsums(int* __restrict__ off, const int* __restrict__ bsum, int n) {
    int gid = blockIdx.x * 1024 + threadIdx.x;
    if (gid < n) off[gid + 1] += bsum[blockIdx.x];
}

__global__ void fill_adj(const int* __restrict__ es, const int* __restrict__ ed,
                         int* __restrict__ cur_u, int* __restrict__ cur_r,
                         int* __restrict__ adj_u, int* __restrict__ adj_r, int E) {
    int e = blockIdx.x * blockDim.x + threadIdx.x;
    if (e < E) {
        int s = es[e], d = ed[e];
        adj_r[atomicAdd(&cur_r[d], 1)] = s;
        adj_u[atomicAdd(&cur_u[s], 1)] = d;
    }
}

// ---------------- scatter-mean as gather (one warp per dst node, H=128) ----------------
__global__ void aggregate_mean(const float* __restrict__ feat,
                               const int* __restrict__ off, const int* __restrict__ adj,
                               float* __restrict__ out, int n) {
    int w = (blockIdx.x * blockDim.x + threadIdx.x) >> 5;
    if (w >= n) return;
    int lane = threadIdx.x & 31;
    int s = off[w], e = off[w + 1];
    float4 acc = make_float4(0.f, 0.f, 0.f, 0.f);
    for (int i = s; i < e; i++) {
        int nb = __ldg(&adj[i]);
        float4 v = *reinterpret_cast<const float4*>(&feat[(size_t)nb * HDIM + lane * 4]);
        acc.x += v.x; acc.y += v.y; acc.z += v.z; acc.w += v.w;
    }
    float inv = (e > s) ? 1.f / (float)(e - s) : 0.f;
    acc.x *= inv; acc.y *= inv; acc.z *= inv; acc.w *= inv;
    *reinterpret_cast<float4*>(&out[(size_t)w * HDIM + lane * 4]) = acc;
}

// ---------------- decoder ----------------
__global__ void decoder_kernel(const float* __restrict__ zu, const float* __restrict__ zr,
                               const int* __restrict__ ls, const int* __restrict__ ld,
                               float* __restrict__ out, int L) {
    int w = (blockIdx.x * blockDim.x + threadIdx.x) >> 5;
    if (w >= L) return;
    int lane = threadIdx.x & 31;
    int s = __ldg(&ls[w]), d = __ldg(&ld[w]);
    float2 a = *reinterpret_cast<const float2*>(&zu[(size_t)s * OUTDIM + lane * 2]);
    float2 b = *reinterpret_cast<const float2*>(&zr[(size_t)d * OUTDIM + lane * 2]);
    float dot = a.x * b.x + a.y * b.y;
    float na = a.x * a.x + a.y * a.y;
    float nb = b.x * b.x + b.y * b.y;
    #pragma unroll
    for (int o = 16; o > 0; o >>= 1) {
        dot += __shfl_xor_sync(0xffffffffu, dot, o);
        na  += __shfl_xor_sync(0xffffffffu, na, o);
        nb  += __shfl_xor_sync(0xffffffffu, nb, o);
    }
    if (lane == 0)
        out[w] = dot / (fmaxf(sqrtf(na), 1e-12f) * fmaxf(sqrtf(nb), 1e-12f));
}

// ---------------- launch ----------------
extern "C" void kernel_launch(void* const* d_in, const int* in_sizes, int n_in,
                              void* d_out, int out_size) {
    const float* x_user   = (const float*)d_in[0];
    const float* x_recipe = (const float*)d_in[1];
    const int* edge_src = (const int*)d_in[2];
    const int* edge_dst = (const int*)d_in[3];
    const int* lbl_src  = (const int*)d_in[4];
    const int* lbl_dst  = (const int*)d_in[5];
    const float* Wu   = (const float*)d_in[6];
    const float* bu   = (const float*)d_in[7];
    const float* Wrec = (const float*)d_in[8];
    const float* brec = (const float*)d_in[9];
    const float* c1urWl = (const float*)d_in[10];
    const float* c1urbl = (const float*)d_in[11];
    const float* c1urWr = (const float*)d_in[12];
    const float* c1ruWl = (const float*)d_in[13];
    const float* c1rubl = (const float*)d_in[14];
    const float* c1ruWr = (const float*)d_in[15];
    const float* c2urWl = (const float*)d_in[16];
    const float* c2urbl = (const float*)d_in[17];
    const float* c2urWr = (const float*)d_in[18];
    const float* c2ruWl = (const float*)d_in[19];
    const float* c2rubl = (const float*)d_in[20];
    const float* c2ruWr = (const float*)d_in[21];
    float* out = (float*)d_out;

    float *hu, *hr, *mean_r, *mean_u, *r1, *u1, *mr2, *mu2, *zr, *zu, *wts;
    int *off_r, *off_u, *cur_r, *cur_u, *adj_r, *adj_u, *bs_r, *bs_u;
    cudaGetSymbolAddress((void**)&hu, g_hu);
    cudaGetSymbolAddress((void**)&hr, g_hr);
    cudaGetSymbolAddress((void**)&mean_r, g_mean_r);
    cudaGetSymbolAddress((void**)&mean_u, g_mean_u);
    cudaGetSymbolAddress((void**)&r1, g_r1);
    cudaGetSymbolAddress((void**)&u1, g_u1);
    cudaGetSymbolAddress((void**)&mr2, g_mr2);
    cudaGetSymbolAddress((void**)&mu2, g_mu2);
    cudaGetSymbolAddress((void**)&zr, g_zr);
    cudaGetSymbolAddress((void**)&zu, g_zu);
    cudaGetSymbolAddress((void**)&wts, g_wts);
    cudaGetSymbolAddress((void**)&off_r, g_off_r);
    cudaGetSymbolAddress((void**)&off_u, g_off_u);
    cudaGetSymbolAddress((void**)&cur_r, g_cur_r);
    cudaGetSymbolAddress((void**)&cur_u, g_cur_u);
    cudaGetSymbolAddress((void**)&adj_r, g_adj_r);
    cudaGetSymbolAddress((void**)&adj_u, g_adj_u);
    cudaGetSymbolAddress((void**)&bs_r, g_bsum_r);
    cudaGetSymbolAddress((void**)&bs_u, g_bsum_u);

    // tf32 weight views in scratch
    const float* tWu     = wts;
    const float* tWrec   = wts + 16384;
    const float* tc1urWl = wts + 49152;
    const float* tc1urWr = wts + 65536;
    const float* tc1ruWl = wts + 81920;
    const float* tc1ruWr = wts + 98304;
    const float* tc2urWl = wts + 114688;
    const float* tc2urWr = wts + 122880;
    const float* tc2ruWl = wts + 131072;
    const float* tc2ruWr = wts + 139264;

    const int SM_H = 2 * (128 * 36 + 128 * 36) * 4;  // 73728 B (J=128)
    const int SM_O = 2 * (128 * 36 + 64 * 36) * 4;   // 55296 B (J=64)
    cudaFuncSetAttribute(gemm_mma<128, 0, 128, false>,
                         cudaFuncAttributeMaxDynamicSharedMemorySize, SM_H);
    cudaFuncSetAttribute(gemm_mma<256, 0, 128, false>,
                         cudaFuncAttributeMaxDynamicSharedMemorySize, SM_H);
    cudaFuncSetAttribute(gemm_mma<128, 128, 128, true>,
                         cudaFuncAttributeMaxDynamicSharedMemorySize, SM_H);
    cudaFuncSetAttribute(gemm_mma<128, 128, 64, false>,
                         cudaFuncAttributeMaxDynamicSharedMemorySize, SM_O);

    const int CH_U = (N_USERS + 1023) / 1024;
    const int CH_R = (N_RECIPES + 1023) / 1024;
    const int GB_U = (N_USERS + 127) / 128;
    const int GB_R = (N_RECIPES + 127) / 128;

    // #1 weight prep (needed by all GEMMs)
    prep_weights<<<(W_TOTAL + 255) / 256, 256>>>(
        Wu, Wrec, c1urWl, c1urWr, c1ruWl, c1ruWr,
        c2urWl, c2urWr, c2ruWl, c2ruWr, wts);

    // #2-#5 CSR front half
    zero_int<<<(N_USERS + 255) / 256, 256>>>(cur_u, N_USERS);
    zero_int<<<(N_RECIPES + 255) / 256, 256>>>(cur_r, N_RECIPES);
    count_deg<<<(NE + 255) / 256, 256>>>(edge_src, edge_dst, cur_u, cur_r, NE);
    scan_chunks<<<CH_U, 1024>>>(cur_u, off_u, bs_u, N_USERS);

    // #6 — biggest GEMM here so ncu (-s 5 -c 1) profiles it
    gemm_mma<128, 0, 128, false><<<GB_U, 256, SM_H>>>(
        x_user, tWu, nullptr, nullptr, bu, hu, N_USERS);

    // CSR rest
    scan_bsums<<<1, 1>>>(bs_u, CH_U);
    add_bsums<<<CH_U, 1024>>>(off_u, bs_u, N_USERS);
    scan_chunks<<<CH_R, 1024>>>(cur_r, off_r, bs_r, N_RECIPES);
    scan_bsums<<<1, 1>>>(bs_r, CH_R);
    add_bsums<<<CH_R, 1024>>>(off_r, bs_r, N_RECIPES);
    copy_int<<<(N_USERS + 255) / 256, 256>>>(cur_u, off_u, N_USERS);
    copy_int<<<(N_RECIPES + 255) / 256, 256>>>(cur_r, off_r, N_RECIPES);
    fill_adj<<<(NE + 255) / 256, 256>>>(edge_src, edge_dst, cur_u, cur_r, adj_u, adj_r, NE);

    gemm_mma<256, 0, 128, false><<<GB_R, 256, SM_H>>>(
        x_recipe, tWrec, nullptr, nullptr, brec, hr, N_RECIPES);

    // --- conv1 ---
    aggregate_mean<<<(N_RECIPES * 32 + 255) / 256, 256>>>(hu, off_r, adj_r, mean_r, N_RECIPES);
    aggregate_mean<<<(N_USERS * 32 + 255) / 256, 256>>>(hr, off_u, adj_u, mean_u, N_USERS);
    gemm_mma<128, 128, 128, true><<<GB_R, 256, SM_H>>>(
        mean_r, tc1urWl, hr, tc1urWr, c1urbl, r1, N_RECIPES);
    gemm_mma<128, 128, 128, true><<<GB_U, 256, SM_H>>>(
        mean_u, tc1ruWl, hu, tc1ruWr, c1rubl, u1, N_USERS);

    // --- conv2 ---
    aggregate_mean<<<(N_RECIPES * 32 + 255) / 256, 256>>>(u1, off_r, adj_r, mr2, N_RECIPES);
    aggregate_mean<<<(N_USERS * 32 + 255) / 256, 256>>>(r1, off_u, adj_u, mu2, N_USERS);
    gemm_mma<128, 128, 64, false><<<GB_R, 256, SM_O>>>(
        mr2, tc2urWl, r1, tc2urWr, c2urbl, zr, N_RECIPES);
    gemm_mma<128, 128, 64, false><<<GB_U, 256, SM_O>>>(
        mu2, tc2ruWl, u1, tc2ruWr, c2rubl, zu, N_USERS);

    // --- decoder ---
    decoder_kernel<<<(NL + 7) / 8, 256>>>(zu, zr, lbl_src, lbl_dst, out, NL);
}

// round 5
// speedup vs baseline: 3.0368x; 1.0941x over previous
#include <cuda_runtime.h>
#include <math.h>
#include <stdint.h>

#define N_USERS   100000
#define N_RECIPES 50000
#define NE        600000
#define NL        200000
#define HDIM      128
#define OUTDIM    64

// ---------------- scratch (no allocation allowed) ----------------
__device__ __align__(128) float g_hu[(size_t)N_USERS * HDIM];
__device__ __align__(128) float g_hr[(size_t)N_RECIPES * HDIM];
__device__ __align__(128) float g_mean_r[(size_t)N_RECIPES * HDIM];
__device__ __align__(128) float g_mean_u[(size_t)N_USERS * HDIM];
__device__ __align__(128) float g_r1[(size_t)N_RECIPES * HDIM];
__device__ __align__(128) float g_u1[(size_t)N_USERS * HDIM];
__device__ __align__(128) float g_mr2[(size_t)N_RECIPES * HDIM];
__device__ __align__(128) float g_mu2[(size_t)N_USERS * HDIM];
__device__ __align__(128) float g_zr[(size_t)N_RECIPES * OUTDIM];
__device__ __align__(128) float g_zu[(size_t)N_USERS * OUTDIM];

__device__ __align__(128) int g_off_r[N_RECIPES + 1];
__device__ __align__(128) int g_off_u[N_USERS + 1];
__device__ __align__(128) int g_cur_r[N_RECIPES];
__device__ __align__(128) int g_cur_u[N_USERS];
__device__ __align__(128) int g_adj_r[NE];
__device__ __align__(128) int g_adj_u[NE];
__device__ __align__(128) int g_bsum_r[64];
__device__ __align__(128) int g_bsum_u[128];

// pre-rounded tf32 weights
#define W_TOTAL 147456
__device__ __align__(128) float g_wts[W_TOTAL];

// ---------------- tf32 mma helpers ----------------
__device__ __forceinline__ float f2tf32(float f) {
    uint32_t r;
    asm("cvt.rna.tf32.f32 %0, %1;" : "=r"(r) : "f"(f));
    return __uint_as_float(r);
}

__device__ __forceinline__ float4 cvt4(float4 v) {
    return make_float4(f2tf32(v.x), f2tf32(v.y), f2tf32(v.z), f2tf32(v.w));
}

__device__ __forceinline__ void mma_tf32(float* d,
                                         uint32_t a0, uint32_t a1, uint32_t a2, uint32_t a3,
                                         uint32_t b0, uint32_t b1) {
    asm volatile(
        "mma.sync.aligned.m16n8k8.row.col.f32.tf32.tf32.f32 "
        "{%0,%1,%2,%3}, {%4,%5,%6,%7}, {%8,%9}, {%0,%1,%2,%3};"
        : "+f"(d[0]), "+f"(d[1]), "+f"(d[2]), "+f"(d[3])
        : "r"(a0), "r"(a1), "r"(a2), "r"(a3), "r"(b0), "r"(b1));
}

__device__ __forceinline__ void cp_async16(uint32_t smem_dst, const void* gsrc) {
    asm volatile("cp.async.ca.shared.global [%0], [%1], 16;"
                 :: "r"(smem_dst), "l"(gsrc) : "memory");
}

// ---------------- weight prep ----------------
__global__ void prep_weights(const float* __restrict__ w0, const float* __restrict__ w1,
                             const float* __restrict__ w2, const float* __restrict__ w3,
                             const float* __restrict__ w4, const float* __restrict__ w5,
                             const float* __restrict__ w6, const float* __restrict__ w7,
                             const float* __restrict__ w8, const float* __restrict__ w9,
                             float* __restrict__ wts) {
    int i = blockIdx.x * blockDim.x + threadIdx.x;
    const float* src; int off;
    if      (i <  16384) { src = w0; off = 0;      }
    else if (i <  49152) { src = w1; off = 16384;  }
    else if (i <  65536) { src = w2; off = 49152;  }
    else if (i <  81920) { src = w3; off = 65536;  }
    else if (i <  98304) { src = w4; off = 81920;  }
    else if (i < 114688) { src = w5; off = 98304;  }
    else if (i < 122880) { src = w6; off = 114688; }
    else if (i < 131072) { src = w7; off = 122880; }
    else if (i < 139264) { src = w8; off = 131072; }
    else if (i < W_TOTAL){ src = w9; off = 139264; }
    else return;
    wts[i] = f2tf32(src[i - off]);
}

// ---------------- combined two-sided tf32 GEMM ----------------
// side: out[n, J] = A[n, *] @ WA^T (+ B @ WB^T) + bias (+relu), runtime strides
struct GSide {
    const float *A, *WA, *B, *WB, *bias;
    float *out;
    int n, lda, ldwa, ldb, ldwb, nch, cha;
};

template <int J, bool RELU>
__global__ __launch_bounds__(256, 2)
void gemm_mma(GSide s0, GSide s1, int split) {
    constexpr int LDS = 36;
    constexpr int NT  = J / 16;
    constexpr int WI  = (J * 8) / 256;

    extern __shared__ float sm[];
    float* AsB = sm;                        // [2][128][LDS]
    float* WsB = sm + 2 * 128 * LDS;        // [2][J][LDS]

    const bool second = (blockIdx.x >= split);
    const GSide s = second ? s1 : s0;
    const int bid = second ? (blockIdx.x - split) : blockIdx.x;
    const int row0 = bid * 128;

    const int tid  = threadIdx.x;
    const int lane = tid & 31;
    const int wid  = tid >> 5;
    const int wm   = wid & 3;
    const int wn   = wid >> 2;
    const int qr   = lane >> 2;
    const int qc   = lane & 3;

    float acc[2][NT][4];
    #pragma unroll
    for (int mt = 0; mt < 2; mt++)
        #pragma unroll
        for (int nt = 0; nt < NT; nt++)
            #pragma unroll
            for (int q = 0; q < 4; q++) acc[mt][nt][q] = 0.f;

    float4 pa[4];

    auto fetchA = [&](int c) {
        const float* src = (c < s.cha) ? s.A : s.B;
        const int ld = (c < s.cha) ? s.lda : s.ldb;
        const int k0 = ((c < s.cha) ? c : c - s.cha) * 32;
        #pragma unroll
        for (int i = 0; i < 4; i++) {
            int lin = tid + i * 256;
            int r = lin >> 3, q = lin & 7;
            int gr = row0 + r;
            pa[i] = (gr < s.n)
                ? *reinterpret_cast<const float4*>(&src[(size_t)gr * ld + k0 + q * 4])
                : make_float4(0.f, 0.f, 0.f, 0.f);
        }
    };

    auto issueW = [&](int c, int b) {
        const float* w = (c < s.cha) ? s.WA : s.WB;
        const int ld = (c < s.cha) ? s.ldwa : s.ldwb;
        const int k0 = ((c < s.cha) ? c : c - s.cha) * 32;
        uint32_t wbase = (uint32_t)__cvta_generic_to_shared(WsB + b * J * LDS);
        #pragma unroll
        for (int i = 0; i < WI; i++) {
            int lin = tid + i * 256;
            int j = lin >> 3, q = lin & 7;
            cp_async16(wbase + (uint32_t)(j * LDS + q * 4) * 4,
                       &w[(size_t)j * ld + k0 + q * 4]);
        }
        asm volatile("cp.async.commit_group;" ::: "memory");
    };

    auto storeA = [&](int b) {
        float* as = AsB + b * 128 * LDS;
        #pragma unroll
        for (int i = 0; i < 4; i++) {
            int lin = tid + i * 256;
            int r = lin >> 3, q = lin & 7;
            *reinterpret_cast<float4*>(&as[r * LDS + q * 4]) = cvt4(pa[i]);
        }
    };

    const int nch = s.nch;
    fetchA(0);
    issueW(0, 0);
    storeA(0);
    asm volatile("cp.async.wait_group 0;" ::: "memory");
    __syncthreads();

    for (int c = 0; c < nch; ++c) {
        const int b = c & 1;
        if (c + 1 < nch) {
            fetchA(c + 1);
            issueW(c + 1, b ^ 1);
        }

        const float* as = AsB + b * 128 * LDS + (wm * 32) * LDS;
        const float* ws = WsB + b * J * LDS + (wn * NT * 8) * LDS;

        #pragma unroll
        for (int ks = 0; ks < 4; ++ks) {
            const int k0 = ks * 8 + qc;
            uint32_t af[2][4];
            #pragma unroll
            for (int mt = 0; mt < 2; mt++) {
                const float* ap = as + (mt * 16 + qr) * LDS;
                af[mt][0] = __float_as_uint(ap[k0]);
                af[mt][1] = __float_as_uint(ap[8 * LDS + k0]);
                af[mt][2] = __float_as_uint(ap[k0 + 4]);
                af[mt][3] = __float_as_uint(ap[8 * LDS + k0 + 4]);
            }
            uint32_t bf[NT][2];
            #pragma unroll
            for (int nt = 0; nt < NT; nt++) {
                const float* bp = ws + (nt * 8 + qr) * LDS;
                bf[nt][0] = __float_as_uint(bp[k0]);
                bf[nt][1] = __float_as_uint(bp[k0 + 4]);
            }
            #pragma unroll
            for (int mt = 0; mt < 2; mt++)
                #pragma unroll
                for (int nt = 0; nt < NT; nt++)
                    mma_tf32(acc[mt][nt],
                             af[mt][0], af[mt][1], af[mt][2], af[mt][3],
                             bf[nt][0], bf[nt][1]);
        }

        if (c + 1 < nch) {
            storeA(b ^ 1);
            asm volatile("cp.async.wait_group 0;" ::: "memory");
            __syncthreads();
        }
    }

    #pragma unroll
    for (int mt = 0; mt < 2; mt++) {
        #pragma unroll
        for (int nt = 0; nt < NT; nt++) {
            int gcol = wn * NT * 8 + nt * 8 + 2 * qc;
            float bx = __ldg(&s.bias[gcol]), by = __ldg(&s.bias[gcol + 1]);
            int r0 = row0 + wm * 32 + mt * 16 + qr;
            float v0 = acc[mt][nt][0] + bx, v1 = acc[mt][nt][1] + by;
            float v2 = acc[mt][nt][2] + bx, v3 = acc[mt][nt][3] + by;
            if (RELU) {
                v0 = fmaxf(v0, 0.f); v1 = fmaxf(v1, 0.f);
                v2 = fmaxf(v2, 0.f); v3 = fmaxf(v3, 0.f);
            }
            if (r0 < s.n)
                *reinterpret_cast<float2*>(&s.out[(size_t)r0 * J + gcol]) = make_float2(v0, v1);
            if (r0 + 8 < s.n)
                *reinterpret_cast<float2*>(&s.out[(size_t)(r0 + 8) * J + gcol]) = make_float2(v2, v3);
        }
    }
}

// ---------------- merged small utility kernels ----------------
__global__ void zero_int2(int* __restrict__ p0, int n0, int* __restrict__ p1, int n1) {
    int i = blockIdx.x * blockDim.x + threadIdx.x;
    if (i < n0) p0[i] = 0;
    else if (i < n0 + n1) p1[i - n0] = 0;
}

__global__ void copy_int2(int* __restrict__ d0, const int* __restrict__ s0, int n0,
                          int* __restrict__ d1, const int* __restrict__ s1, int n1) {
    int i = blockIdx.x * blockDim.x + threadIdx.x;
    if (i < n0) d0[i] = s0[i];
    else if (i < n0 + n1) d1[i - n0] = s1[i - n0];
}

__global__ void count_deg(const int* __restrict__ es, const int* __restrict__ ed,
                          int* __restrict__ deg_u, int* __restrict__ deg_r, int E) {
    int e = blockIdx.x * blockDim.x + threadIdx.x;
    if (e < E) {
        atomicAdd(&deg_u[es[e]], 1);
        atomicAdd(&deg_r[ed[e]], 1);
    }
}

__global__ void scan_chunks2(const int* __restrict__ dg0, int* __restrict__ of0,
                             int* __restrict__ bs0, int n0, int nb0,
                             const int* __restrict__ dg1, int* __restrict__ of1,
                             int* __restrict__ bs1, int n1) {
    const int* deg; int* off; int* bsum; int n, lb;
    if ((int)blockIdx.x < nb0) { deg = dg0; off = of0; bsum = bs0; n = n0; lb = blockIdx.x; }
    else { deg = dg1; off = of1; bsum = bs1; n = n1; lb = blockIdx.x - nb0; }
    __shared__ int sh[1024];
    int t = threadIdx.x;
    int gid = lb * 1024 + t;
    int v = (gid < n) ? deg[gid] : 0;
    sh[t] = v;
    __syncthreads();
    #pragma unroll
    for (int d = 1; d < 1024; d <<= 1) {
        int add = (t >= d) ? sh[t - d] : 0;
        __syncthreads();
        sh[t] += add;
        __syncthreads();
    }
    if (gid < n) off[gid + 1] = sh[t];
    if (t == 1023) bsum[lb] = sh[1023];
    if (gid == 0) off[0] = 0;
}

__global__ void scan_bsums2(int* __restrict__ b0, int nb0, int* __restrict__ b1, int nb1) {
    if (threadIdx.x != 0) return;
    int* b = (blockIdx.x == 0) ? b0 : b1;
    int nb = (blockIdx.x == 0) ? nb0 : nb1;
    int acc = 0;
    for (int i = 0; i < nb; i++) { int t = b[i]; b[i] = acc; acc += t; }
}

__global__ void add_bsums2(int* __restrict__ of0, const int* __restrict__ bs0, int n0, int nb0,
                           int* __restrict__ of1, const int* __restrict__ bs1, int n1) {
    int* off; const int* bsum; int n, lb;
    if ((int)blockIdx.x < nb0) { off = of0; bsum = bs0; n = n0; lb = blockIdx.x; }
    else { off = of1; bsum = bs1; n = n1; lb = blockIdx.x - nb0; }
    int gid = lb * 1024 + threadIdx.x;
    if (gid < n) off[gid + 1] += bsum[lb];
}

__global__ void fill_adj(const int* __restrict__ es, const int* __restrict__ ed,
                         int* __restrict__ cur_u, int* __restrict__ cur_r,
                         int* __restrict__ adj_u, int* __restrict__ adj_r, int E) {
    int e = blockIdx.x * blockDim.x + threadIdx.x;
    if (e < E) {
        int s = es[e], d = ed[e];
        adj_r[atomicAdd(&cur_r[d], 1)] = s;
        adj_u[atomicAdd(&cur_u[s], 1)] = d;
    }
}

// ---------------- merged scatter-mean (both sides in one grid) ----------------
__global__ void aggregate_mean2(
    const float* __restrict__ f0, const int* __restrict__ o0,
    const int* __restrict__ a0, float* __restrict__ out0, int n0,
    const float* __restrict__ f1, const int* __restrict__ o1,
    const int* __restrict__ a1, float* __restrict__ out1, int n1) {
    int w = (blockIdx.x * blockDim.x + threadIdx.x) >> 5;
    const float* feat; const int* off; const int* adj; float* out;
    if (w < n0) { feat = f0; off = o0; adj = a0; out = out0; }
    else {
        w -= n0;
        if (w >= n1) return;
        feat = f1; off = o1; adj = a1; out = out1;
    }
    int lane = threadIdx.x & 31;
    int s = off[w], e = off[w + 1];
    float4 acc = make_float4(0.f, 0.f, 0.f, 0.f);
    for (int i = s; i < e; i++) {
        int nb = __ldg(&adj[i]);
        float4 v = *reinterpret_cast<const float4*>(&feat[(size_t)nb * HDIM + lane * 4]);
        acc.x += v.x; acc.y += v.y; acc.z += v.z; acc.w += v.w;
    }
    float inv = (e > s) ? 1.f / (float)(e - s) : 0.f;
    acc.x *= inv; acc.y *= inv; acc.z *= inv; acc.w *= inv;
    *reinterpret_cast<float4*>(&out[(size_t)w * HDIM + lane * 4]) = acc;
}

// ---------------- decoder ----------------
__global__ void decoder_kernel(const float* __restrict__ zu, const float* __restrict__ zr,
                               const int* __restrict__ ls, const int* __restrict__ ld,
                               float* __restrict__ out, int L) {
    int w = (blockIdx.x * blockDim.x + threadIdx.x) >> 5;
    if (w >= L) return;
    int lane = threadIdx.x & 31;
    int s = __ldg(&ls[w]), d = __ldg(&ld[w]);
    float2 a = *reinterpret_cast<const float2*>(&zu[(size_t)s * OUTDIM + lane * 2]);
    float2 b = *reinterpret_cast<const float2*>(&zr[(size_t)d * OUTDIM + lane * 2]);
    float dot = a.x * b.x + a.y * b.y;
    float na = a.x * a.x + a.y * a.y;
    float nb = b.x * b.x + b.y * b.y;
    #pragma unroll
    for (int o = 16; o > 0; o >>= 1) {
        dot += __shfl_xor_sync(0xffffffffu, dot, o);
        na  += __shfl_xor_sync(0xffffffffu, na, o);
        nb  += __shfl_xor_sync(0xffffffffu, nb, o);
    }
    if (lane == 0)
        out[w] = dot / (fmaxf(sqrtf(na), 1e-12f) * fmaxf(sqrtf(nb), 1e-12f));
}

// ---------------- launch ----------------
extern "C" void kernel_launch(void* const* d_in, const int* in_sizes, int n_in,
                              void* d_out, int out_size) {
    const float* x_user   = (const float*)d_in[0];
    const float* x_recipe = (const float*)d_in[1];
    const int* edge_src = (const int*)d_in[2];
    const int* edge_dst = (const int*)d_in[3];
    const int* lbl_src  = (const int*)d_in[4];
    const int* lbl_dst  = (const int*)d_in[5];
    const float* Wu   = (const float*)d_in[6];
    const float* bu   = (const float*)d_in[7];
    const float* Wrec = (const float*)d_in[8];
    const float* brec = (const float*)d_in[9];
    const float* c1urWl = (const float*)d_in[10];
    const float* c1urbl = (const float*)d_in[11];
    const float* c1urWr = (const float*)d_in[12];
    const float* c1ruWl = (const float*)d_in[13];
    const float* c1rubl = (const float*)d_in[14];
    const float* c1ruWr = (const float*)d_in[15];
    const float* c2urWl = (const float*)d_in[16];
    const float* c2urbl = (const float*)d_in[17];
    const float* c2urWr = (const float*)d_in[18];
    const float* c2ruWl = (const float*)d_in[19];
    const float* c2rubl = (const float*)d_in[20];
    const float* c2ruWr = (const float*)d_in[21];
    float* out = (float*)d_out;

    float *hu, *hr, *mean_r, *mean_u, *r1, *u1, *mr2, *mu2, *zr, *zu, *wts;
    int *off_r, *off_u, *cur_r, *cur_u, *adj_r, *adj_u, *bs_r, *bs_u;
    cudaGetSymbolAddress((void**)&hu, g_hu);
    cudaGetSymbolAddress((void**)&hr, g_hr);
    cudaGetSymbolAddress((void**)&mean_r, g_mean_r);
    cudaGetSymbolAddress((void**)&mean_u, g_mean_u);
    cudaGetSymbolAddress((void**)&r1, g_r1);
    cudaGetSymbolAddress((void**)&u1, g_u1);
    cudaGetSymbolAddress((void**)&mr2, g_mr2);
    cudaGetSymbolAddress((void**)&mu2, g_mu2);
    cudaGetSymbolAddress((void**)&zr, g_zr);
    cudaGetSymbolAddress((void**)&zu, g_zu);
    cudaGetSymbolAddress((void**)&wts, g_wts);
    cudaGetSymbolAddress((void**)&off_r, g_off_r);
    cudaGetSymbolAddress((void**)&off_u, g_off_u);
    cudaGetSymbolAddress((void**)&cur_r, g_cur_r);
    cudaGetSymbolAddress((void**)&cur_u, g_cur_u);
    cudaGetSymbolAddress((void**)&adj_r, g_adj_r);
    cudaGetSymbolAddress((void**)&adj_u, g_adj_u);
    cudaGetSymbolAddress((void**)&bs_r, g_bsum_r);
    cudaGetSymbolAddress((void**)&bs_u, g_bsum_u);

    // tf32 weight views
    const float* tWu     = wts;
    const float* tWrec   = wts + 16384;
    const float* tc1urWl = wts + 49152;
    const float* tc1urWr = wts + 65536;
    const float* tc1ruWl = wts + 81920;
    const float* tc1ruWr = wts + 98304;
    const float* tc2urWl = wts + 114688;
    const float* tc2urWr = wts + 122880;
    const float* tc2ruWl = wts + 131072;
    const float* tc2ruWr = wts + 139264;

    const int SM_H = 2 * (128 * 36 + 128 * 36) * 4;  // 73728 B (J=128)
    const int SM_O = 2 * (128 * 36 + 64 * 36) * 4;   // 55296 B (J=64)
    cudaFuncSetAttribute(gemm_mma<128, false>,
                         cudaFuncAttributeMaxDynamicSharedMemorySize, SM_H);
    cudaFuncSetAttribute(gemm_mma<128, true>,
                         cudaFuncAttributeMaxDynamicSharedMemorySize, SM_H);
    cudaFuncSetAttribute(gemm_mma<64, false>,
                         cudaFuncAttributeMaxDynamicSharedMemorySize, SM_O);

    const int CH_U = (N_USERS + 1023) / 1024;    // 98
    const int CH_R = (N_RECIPES + 1023) / 1024;  // 49
    const int GB_U = (N_USERS + 127) / 128;      // 782
    const int GB_R = (N_RECIPES + 127) / 128;    // 391

    // GEMM side descriptors
    GSide proj_r = { x_recipe, tWrec, x_recipe + 128, tWrec + 128, brec, hr,
                     N_RECIPES, 256, 256, 256, 256, 8, 4 };
    GSide proj_u = { x_user, tWu, x_user, tWu, bu, hu,
                     N_USERS, 128, 128, 128, 128, 4, 4 };
    GSide c1_r = { mean_r, tc1urWl, hr, tc1urWr, c1urbl, r1,
                   N_RECIPES, 128, 128, 128, 128, 8, 4 };
    GSide c1_u = { mean_u, tc1ruWl, hu, tc1ruWr, c1rubl, u1,
                   N_USERS, 128, 128, 128, 128, 8, 4 };
    GSide c2_r = { mr2, tc2urWl, r1, tc2urWr, c2urbl, zr,
                   N_RECIPES, 128, 128, 128, 128, 8, 4 };
    GSide c2_u = { mu2, tc2ruWl, u1, tc2ruWr, c2rubl, zu,
                   N_USERS, 128, 128, 128, 128, 8, 4 };

    // #1 weight prep
    prep_weights<<<(W_TOTAL + 255) / 256, 256>>>(
        Wu, Wrec, c1urWl, c1urWr, c1ruWl, c1ruWr,
        c2urWl, c2urWr, c2ruWl, c2ruWr, wts);

    // #2-#3 CSR front
    zero_int2<<<(N_USERS + N_RECIPES + 255) / 256, 256>>>(cur_u, N_USERS, cur_r, N_RECIPES);
    count_deg<<<(NE + 255) / 256, 256>>>(edge_src, edge_dst, cur_u, cur_r, NE);

    // #4 combined input projections (ncu target)
    gemm_mma<128, false><<<GB_R + GB_U, 256, SM_H>>>(proj_r, proj_u, GB_R);

    // CSR rest
    scan_chunks2<<<CH_U + CH_R, 1024>>>(cur_u, off_u, bs_u, N_USERS, CH_U,
                                        cur_r, off_r, bs_r, N_RECIPES);
    scan_bsums2<<<2, 32>>>(bs_u, CH_U, bs_r, CH_R);
    add_bsums2<<<CH_U + CH_R, 1024>>>(off_u, bs_u, N_USERS, CH_U,
                                      off_r, bs_r, N_RECIPES);
    copy_int2<<<(N_USERS + N_RECIPES + 255) / 256, 256>>>(cur_u, off_u, N_USERS,
                                                          cur_r, off_r, N_RECIPES);
    fill_adj<<<(NE + 255) / 256, 256>>>(edge_src, edge_dst, cur_u, cur_r, adj_u, adj_r, NE);

    // conv1
    aggregate_mean2<<<((N_RECIPES + N_USERS) * 32 + 255) / 256, 256>>>(
        hu, off_r, adj_r, mean_r, N_RECIPES,
        hr, off_u, adj_u, mean_u, N_USERS);
    gemm_mma<128, true><<<GB_R + GB_U, 256, SM_H>>>(c1_r, c1_u, GB_R);

    // conv2
    aggregate_mean2<<<((N_RECIPES + N_USERS) * 32 + 255) / 256, 256>>>(
        u1, off_r, adj_r, mr2, N_RECIPES,
        r1, off_u, adj_u, mu2, N_USERS);
    gemm_mma<64, false><<<GB_R + GB_U, 256, SM_O>>>(c2_r, c2_u, GB_R);

    // decoder
    decoder_kernel<<<(NL + 7) / 8, 256>>>(zu, zr, lbl_src, lbl_dst, out, NL);
}